// round 8
// baseline (speedup 1.0000x reference)
#include <cuda_runtime.h>
#include <math.h>

// Problem constants (B=4, S=2048, D_IN=1024, D_OUT=1024, E=8, K=2)
#define BTOK    8192
#define DIN     1024
#define DOUT    1024
#define NE      8
#define NROW    24          // 8 gate rows + 16 expert rows (e, o in {0,1})
#define SPLITK  8
#define KSPAN   (DIN / SPLITK)   // 128 k per block
#define CH      16          // k per register chunk (64 B per thread)
#define NCH     (KSPAN / CH)     // 8 chunks
#define TPB     128         // threads = tokens per GEMM block
#define WSS     132         // ws row stride (16B-aligned: 132*4=528)

// Partials: scratch[(split*NROW + row)*BTOK + token]
__device__ float g_scratch[SPLITK * NROW * BTOK];   // 6.3 MB

__device__ __forceinline__ unsigned long long fma2(unsigned long long a,
                                                   unsigned long long b,
                                                   unsigned long long c) {
    unsigned long long d;
    asm("fma.rn.f32x2 %0, %1, %2, %3;" : "=l"(d) : "l"(a), "l"(b), "l"(c));
    return d;
}
__device__ __forceinline__ void unpack2(unsigned long long v, float& lo, float& hi) {
    asm("mov.b64 {%0, %1}, %2;" : "=f"(lo), "=f"(hi) : "l"(v));
}

// ---------------------------------------------------------------------------
// Kernel 1: split-K skinny GEMM. thread = token; x global->regs (double-
// buffered); weights smem broadcast; packed f32x2 FMA. One __syncthreads.
// ---------------------------------------------------------------------------
__global__ __launch_bounds__(TPB)
void moe_gemm_kernel(const float* __restrict__ x,
                     const float* __restrict__ gate_w,
                     const float* __restrict__ expert_w)
{
    __shared__ float ws[NROW][WSS];      // 12672 B

    const int tid   = threadIdx.x;
    const int split = blockIdx.x & (SPLITK - 1);
    const int tb    = blockIdx.x >> 3;
    const int token = tb * TPB + tid;
    const int kbase = split * KSPAN;

    const float* xp = x + (size_t)token * DIN + kbase;

    // x chunk buffers in registers: 2 x 4 x 16B = 64 regs total
    ulonglong2 xb[2][4];

    // prefetch chunk 0 (independent of smem)
    #pragma unroll
    for (int q = 0; q < 4; q++)
        xb[0][q] = *(const ulonglong2*)(xp + q * 4);

    // ---- load weight tile: 24 rows x 128 floats = 768 float4 ----
    #pragma unroll
    for (int j = 0; j < (NROW * KSPAN) / (4 * TPB); j++) {   // 6
        int i   = tid + j * TPB;
        int row = i >> 5;
        int f4  = (i & 31) << 2;
        const float* src = (row < NE)
            ? (gate_w + (size_t)row * DIN)
            : (expert_w + ((size_t)(((row - NE) >> 1) * DOUT + ((row - NE) & 1))) * DIN);
        float4 v = *(const float4*)(src + kbase + f4);
        *(float4*)&ws[row][f4] = v;
    }

    __syncthreads();

    unsigned long long acc[NROW];
    #pragma unroll
    for (int r = 0; r < NROW; r++) acc[r] = 0ULL;

    #pragma unroll
    for (int c = 0; c < NCH; c++) {
        const int cur = c & 1;
        // prefetch next chunk into the other buffer
        if (c + 1 < NCH) {
            const float* np = xp + (c + 1) * CH;
            #pragma unroll
            for (int q = 0; q < 4; q++)
                xb[cur ^ 1][q] = *(const ulonglong2*)(np + q * 4);
        }
        // compute current chunk: 16 k = 4 quads
        #pragma unroll
        for (int q = 0; q < 4; q++) {
            const ulonglong2 xv = xb[cur][q];      // (x0,x1),(x2,x3)
            const int kk = c * CH + q * 4;
            #pragma unroll
            for (int r = 0; r < NROW; r++) {
                ulonglong2 wv = *(const ulonglong2*)(&ws[r][kk]);  // broadcast
                acc[r] = fma2(xv.x, wv.x, acc[r]);
                acc[r] = fma2(xv.y, wv.y, acc[r]);
            }
        }
    }

    // ---- write partials, coalesced: [split][row][token] ----
    #pragma unroll
    for (int r = 0; r < NROW; r++) {
        float lo, hi;
        unpack2(acc[r], lo, hi);
        g_scratch[((size_t)(split * NROW + r)) * BTOK + token] = lo + hi;
    }
}

// ---------------------------------------------------------------------------
// Kernel 2: cell-parallel reduce + gating + broadcast write
// ---------------------------------------------------------------------------
#define ETOK 16
#define ETH  256
#define PST  25

__global__ __launch_bounds__(ETH)
void moe_epilogue_kernel(const float* __restrict__ gate_b,
                         const float* __restrict__ ebias,
                         const float* __restrict__ expert_b,
                         float* __restrict__ out,
                         float* __restrict__ idx_out)
{
    __shared__ float Pfin[ETOK][PST];
    __shared__ float wtok[ETOK];

    const int tid  = threadIdx.x;
    const int tok0 = blockIdx.x * ETOK;

    // ---- reduce: cell = (row, token); 384 cells over 256 threads ----
    #pragma unroll
    for (int c2 = 0; c2 < 2; c2++) {
        int cell = tid + c2 * ETH;
        if (cell < ETOK * NROW) {
            int token = cell & (ETOK - 1);    // fast index -> coalesced lanes
            int row   = cell >> 4;
            const float* src = g_scratch + (size_t)row * BTOK + tok0 + token;
            float s = 0.f;
            #pragma unroll
            for (int sp = 0; sp < SPLITK; sp++)
                s += src[(size_t)(sp * NROW) * BTOK];   // 8 independent loads
            Pfin[token][row] = s;
        }
    }
    __syncthreads();

    // ---- gating (threads 0..15) ----
    if (tid < ETOK) {
        const float* Pm = &Pfin[tid][0];
        float l[NE];
        #pragma unroll
        for (int e = 0; e < NE; e++)
            l[e] = Pm[e] + gate_b[e] + ebias[e];

        int e0 = 0; float b0 = l[0];
        #pragma unroll
        for (int e = 1; e < NE; e++)
            if (l[e] > b0) { b0 = l[e]; e0 = e; }
        int e1 = -1; float b1 = -INFINITY;
        #pragma unroll
        for (int e = 0; e < NE; e++) {
            if (e == e0) continue;
            if (l[e] > b1) { b1 = l[e]; e1 = e; }
        }

        float p0 = 1.f / (1.f + expf(-b0));
        float p1 = 1.f / (1.f + expf(-b1));
        float inv = 1.f / (p0 + p1);

        float v0 = Pm[NE + e0 * 2 + 0] + expert_b[(size_t)e0 * DOUT + 0];
        float v1 = Pm[NE + e1 * 2 + 1] + expert_b[(size_t)e1 * DOUT + 1];
        wtok[tid] = (v0 * p0 + v1 * p1) * inv;

        if (idx_out) {
            idx_out[(size_t)(tok0 + tid) * 2 + 0] = (float)e0;
            idx_out[(size_t)(tok0 + tid) * 2 + 1] = (float)e1;
        }
    }
    __syncthreads();

    // ---- broadcast write: 256 threads x float4 = 1024 floats per token ----
    const int fo = tid << 2;
    #pragma unroll 4
    for (int m = 0; m < ETOK; m++) {
        float v = wtok[m];
        float4 v4 = make_float4(v, v, v, v);
        *(float4*)(out + (size_t)(tok0 + m) * DOUT + fo) = v4;
    }
}

extern "C" void kernel_launch(void* const* d_in, const int* in_sizes, int n_in,
                              void* d_out, int out_size)
{
    const float* x        = (const float*)d_in[0];
    const float* gate_w   = (const float*)d_in[1];
    const float* gate_b   = (const float*)d_in[2];
    const float* ebias    = (const float*)d_in[3];
    const float* expert_w = (const float*)d_in[4];
    const float* expert_b = (const float*)d_in[5];
    float* out = (float*)d_out;

    float* idx_out = nullptr;
    long long base = (long long)BTOK * DOUT;
    if ((long long)out_size >= base + (long long)BTOK * 2)
        idx_out = out + base;

    moe_gemm_kernel<<<(BTOK / TPB) * SPLITK, TPB>>>(x, gate_w, expert_w);
    moe_epilogue_kernel<<<BTOK / ETOK, ETH>>>(gate_b, ebias, expert_b,
                                              out, idx_out);
}